// round 13
// baseline (speedup 1.0000x reference)
#include <cuda_runtime.h>
#include <cuda_fp16.h>
#include <cstdint>
#include <math.h>

// ---------------- problem constants ----------------
#define NTOK   8192
#define DM     1024
#define NE     8
#define NEX    9          // 8 routed + shared-as-expert-8
#define KP     1024       // pure fp16
#define NCH    16         // KP / 64 chunks
#define SHROWS 8192
#define MAXROWS 25600
#define TGRID  208
#define WS     (DM * KP)

// ---------------- device scratch ----------------
__device__ __half g_Xg3[(size_t)MAXROWS * KP];
__device__ __half g_H3 [(size_t)MAXROWS * KP];
__device__ __half g_w13[(size_t)NEX * WS];
__device__ __half g_w23[(size_t)NEX * WS];
__device__ __half g_w33[(size_t)NEX * WS];
__device__ float g_Yg[(size_t)MAXROWS * DM];
__device__ float g_bx1[NEX * DM];
__device__ float g_bx2[NEX * DM];
__device__ float g_bx3[NEX * DM];

__device__ int   g_top_idx[NTOK * 2];
__device__ float g_top_w  [NTOK * 2];
__device__ int   g_slot_row[NTOK * 2];
__device__ int   g_counts[NE];
__device__ int   g_cursor[NE];
__device__ int   g_rowbase[NE];
__device__ int   g_rmap[224];
__device__ int   g_ntiles[1];

// ---------------- helpers ----------------
__device__ __forceinline__ uint32_t smem_u32(const void* p) {
    uint32_t a;
    asm("{ .reg .u64 t; cvta.to.shared.u64 t, %1; cvt.u32.u64 %0, t; }"
        : "=r"(a) : "l"(p));
    return a;
}
__device__ __forceinline__ void cp16(uint32_t dst, const void* src) {
    asm volatile("cp.async.cg.shared.global [%0], [%1], 16;\n"
                 :: "r"(dst), "l"(src) : "memory");
}
__device__ __forceinline__ void ldm_x4(uint32_t* r, uint32_t addr) {
    asm volatile("ldmatrix.sync.aligned.m8n8.x4.shared.b16 {%0,%1,%2,%3}, [%4];"
                 : "=r"(r[0]), "=r"(r[1]), "=r"(r[2]), "=r"(r[3]) : "r"(addr));
}
__device__ __forceinline__ void mma_f16(float* d, const uint32_t* a, const uint32_t* b) {
    asm volatile(
        "mma.sync.aligned.m16n8k16.row.col.f32.f16.f16.f32 "
        "{%0,%1,%2,%3}, {%4,%5,%6,%7}, {%8,%9}, {%0,%1,%2,%3};"
        : "+f"(d[0]), "+f"(d[1]), "+f"(d[2]), "+f"(d[3])
        : "r"(a[0]), "r"(a[1]), "r"(a[2]), "r"(a[3]), "r"(b[0]), "r"(b[1]));
}
__device__ __forceinline__ unsigned short h16(float v) {
    __half h = __float2half_rn(v);
    return *reinterpret_cast<unsigned short*>(&h);
}
__device__ __forceinline__ uint32_t pk(unsigned short a, unsigned short b) {
    return (uint32_t)a | ((uint32_t)b << 16);
}
__device__ __forceinline__ float silu(float x) {
    return x / (1.f + expf(-x));
}

// ---------------- routing kernels (R8 exact) ----------------
__global__ void k_zero()
{
    int i = threadIdx.x;
    if (i < NE) { g_counts[i] = 0; g_cursor[i] = 0; }
}

__global__ void k_gate(const float* __restrict__ x, const float* __restrict__ gw)
{
    int w = threadIdx.x >> 5, lane = threadIdx.x & 31;
    int t = blockIdx.x * 8 + w;
    const float4* xr = (const float4*)(x + (size_t)t * DM);
    float logits[NE];
    #pragma unroll
    for (int e = 0; e < NE; e++) {
        const float4* g = (const float4*)(gw + (size_t)e * DM);
        float s = 0.f;
        #pragma unroll
        for (int d = lane; d < DM/4; d += 32) {
            float4 a = xr[d], b = g[d];
            s += a.x*b.x + a.y*b.y + a.z*b.z + a.w*b.w;
        }
        #pragma unroll
        for (int o = 16; o; o >>= 1) s += __shfl_xor_sync(0xffffffffu, s, o);
        logits[e] = s;
    }
    if (lane == 0) {
        float m = logits[0];
        #pragma unroll
        for (int e = 1; e < NE; e++) m = fmaxf(m, logits[e]);
        float sum = 0.f, p[NE];
        #pragma unroll
        for (int e = 0; e < NE; e++) { p[e] = expf(logits[e] - m); sum += p[e]; }
        int i0 = 0;
        #pragma unroll
        for (int e = 1; e < NE; e++) if (logits[e] > logits[i0]) i0 = e;
        int i1 = (i0 == 0) ? 1 : 0;
        #pragma unroll
        for (int e = 0; e < NE; e++)
            if (e != i0 && logits[e] > logits[i1]) i1 = e;
        float inv = 1.f / sum;
        g_top_idx[2*t]   = i0;  g_top_w[2*t]   = p[i0] * inv;
        g_top_idx[2*t+1] = i1;  g_top_w[2*t+1] = p[i1] * inv;
        atomicAdd(&g_counts[i0], 1);
        atomicAdd(&g_counts[i1], 1);
    }
}

__global__ void k_scan()
{
    if (threadIdx.x == 0) {
        int nt = 0;
        for (int i = 0; i < SHROWS / 128; i++)
            g_rmap[nt++] = (8 << 20) | (i << 7);
        int base = SHROWS;
        for (int e = 0; e < NE; e++) {
            g_rowbase[e] = base;
            int c = g_counts[e];
            int p = ((c + 127) >> 7) << 7;
            for (int i = 0; i < (p >> 7); i++)
                g_rmap[nt++] = (e << 20) | (base + (i << 7));
            base += p;
        }
        g_ntiles[0] = nt;
    }
}

// ---------------- conversion kernels (R8 exact) ----------------
__global__ void k_cvt_a(const float* __restrict__ in, __half* __restrict__ out, int n8)
{
    int q = blockIdx.x * blockDim.x + threadIdx.x;
    if (q >= n8) return;
    float4 v0 = *(const float4*)(in + (size_t)q * 8);
    float4 v1 = *(const float4*)(in + (size_t)q * 8 + 4);
    ((uint4*)out)[q] = make_uint4(pk(h16(v0.x), h16(v0.y)), pk(h16(v0.z), h16(v0.w)),
                                  pk(h16(v1.x), h16(v1.y)), pk(h16(v1.z), h16(v1.w)));
}

__global__ void k_cvt_w(const float* __restrict__ W, __half* __restrict__ out)
{
    __shared__ float tile[32][33];
    int k0 = blockIdx.x << 5, n0 = blockIdx.y << 5;
    const float* Wm = W + (size_t)blockIdx.z * DM * DM;
    char* Om = (char*)out + (size_t)blockIdx.z * DM * (KP*2);
    int tx = threadIdx.x, ty = threadIdx.y;
    #pragma unroll
    for (int i = 0; i < 4; i++)
        tile[ty + i*8][tx] = Wm[(size_t)(k0 + ty + i*8) * DM + n0 + tx];
    __syncthreads();
    int tid = ty * 32 + tx;
    int wn = tid >> 3, wk4 = (tid & 7) << 2;
    char* ob = Om + (size_t)(n0 + wn) * (KP*2) + (size_t)(k0 + wk4) * 2;
    ((uint2*)ob)[0] = make_uint2(pk(h16(tile[wk4+0][wn]), h16(tile[wk4+1][wn])),
                                 pk(h16(tile[wk4+2][wn]), h16(tile[wk4+3][wn])));
}

__global__ void k_biaspack(const float* __restrict__ b1, const float* __restrict__ b3,
                           const float* __restrict__ b2, const float* __restrict__ sb1,
                           const float* __restrict__ sb3, const float* __restrict__ sb2)
{
    int i = blockIdx.x * blockDim.x + threadIdx.x;
    if (i >= NEX * DM) return;
    if (i < NE * DM) {
        g_bx1[i] = b1[i]; g_bx3[i] = b3[i]; g_bx2[i] = b2[i];
    } else {
        int j = i - NE * DM;
        g_bx1[i] = sb1[j]; g_bx3[i] = sb3[j]; g_bx2[i] = sb2[j];
    }
}

__global__ void k_zeropad()
{
    int e = blockIdx.x;
    int c = g_counts[e];
    int p = ((c + 127) >> 7) << 7;
    int r = c + blockIdx.y;
    if (r < p) {
        uint4* row = (uint4*)(g_Xg3 + (size_t)(g_rowbase[e] + r) * KP);
        for (int i = threadIdx.x; i < KP*2/16; i += blockDim.x)
            row[i] = make_uint4(0,0,0,0);
    }
}

__global__ void k_gather()
{
    int slot = blockIdx.x, t = slot >> 1;
    __shared__ int srow;
    if (threadIdx.x == 0) {
        int e  = g_top_idx[slot];
        int rk = atomicAdd(&g_cursor[e], 1);
        int row = g_rowbase[e] + rk;
        g_slot_row[slot] = row;
        srow = row;
    }
    __syncthreads();
    const uint4* src = (const uint4*)(g_Xg3 + (size_t)t * KP);
    uint4*       dst = (uint4*)(g_Xg3 + (size_t)srow * KP);
    for (int i = threadIdx.x; i < KP*2/16; i += blockDim.x) dst[i] = src[i];
}

// ---------------- fused W1/W3 + SiLU GEMM: big tile 128 x (128|128) ----------------
// B in smem = concat [W1 rows c0..c0+127 | W3 rows c0..c0+127] (256 rows x 128B).
// 8 warps: wm in {0,1} (64-row), wn in {0..3} (64-col of concat). wn<2 -> h1, wn>=2 -> h3.
// 2-stage cp.async (48KB/stage). Epilogue: h3 warps stage acc via smem, h1 warps fuse silu.
__global__ __launch_bounds__(256)
void k_gemm13(const __half* __restrict__ A3,
              const __half* __restrict__ W1h, const __half* __restrict__ W3h)
{
    if ((int)blockIdx.x >= g_ntiles[0]) return;
    extern __shared__ char dynsmem[];

    int entry = g_rmap[blockIdx.x];
    int e = entry >> 20, r0 = entry & 0xFFFFF;
    int c0 = blockIdx.y << 7;                 // 128 cols per matrix
    int tid = threadIdx.x, wid = tid >> 5, lane = tid & 31;
    int wm = wid & 1, wn = wid >> 1;

    uint32_t sbase = smem_u32(dynsmem);
    const char* Ag  = (const char*)(A3 + (size_t)r0 * KP);
    const char* B1g = (const char*)(W1h + (size_t)e * WS + (size_t)c0 * KP);
    const char* B3g = (const char*)(W3h + (size_t)e * WS + (size_t)c0 * KP);

    int lrow = tid >> 3, lc = tid & 7;
    uint32_t aoff = (uint32_t)(lrow*128 + ((lc ^ (lrow & 7)) << 4));

    auto load_stage = [&](int s, int ch) {
        uint32_t sa = sbase + s * 49152;
        uint32_t sb = sa + 16384;
        const char* Ac = Ag + ch * 128;
        size_t goff = (size_t)lrow * (KP*2) + lc * 16;
        #pragma unroll
        for (int i = 0; i < 4; i++)
            cp16(sa + aoff + i*4096, Ac + goff + (size_t)i*32*(KP*2));
        #pragma unroll
        for (int i = 0; i < 8; i++) {
            int id = tid + i*256;
            int r = id >> 3, c = id & 7;
            int rl = r & 127;
            uint32_t off = (uint32_t)(rl*128 + ((c ^ (rl & 7)) << 4)) + (i >= 4 ? 16384u : 0u);
            const char* src = (i < 4) ? (B1g + (size_t)rl * (KP*2))
                                      : (B3g + (size_t)rl * (KP*2));
            cp16(sb + off, src + c*16 + (size_t)ch*128);
        }
        asm volatile("cp.async.commit_group;" ::: "memory");
    };

    float acc[4][8][4];
    #pragma unroll
    for (int mt = 0; mt < 4; mt++)
        #pragma unroll
        for (int nt = 0; nt < 8; nt++)
            #pragma unroll
            for (int j = 0; j < 4; j++) acc[mt][nt][j] = 0.f;

    load_stage(0, 0);

    int a_row  = wm*64 + (lane & 15);
    int a_cb   = lane >> 4;
    int b_row0 = wn*64 + ((lane >> 4) << 3) + (lane & 7);
    int b_cb   = (lane >> 3) & 1;

    for (int ch = 0; ch < NCH; ch++) {
        int s = ch & 1;
        if (ch > 0) __syncthreads();                 // prev compute done (it used slot s^1)
        if (ch + 1 < NCH) load_stage(s ^ 1, ch + 1);
        else asm volatile("cp.async.commit_group;" ::: "memory");
        asm volatile("cp.async.wait_group 1;" ::: "memory");
        __syncthreads();

        uint32_t sa = sbase + s * 49152;
        uint32_t sb = sa + 16384;
        #pragma unroll
        for (int kk = 0; kk < 4; kk++) {
            uint32_t a[4][4], b[8][2];
            #pragma unroll
            for (int mt = 0; mt < 4; mt++) {
                int row = a_row + mt*16;
                int c = kk*2 + a_cb;
                ldm_x4(a[mt], sa + row*128 + ((c ^ (row & 7)) << 4));
            }
            #pragma unroll
            for (int np = 0; np < 4; np++) {
                int row = b_row0 + np*16;
                int c = kk*2 + b_cb;
                uint32_t r4[4];
                ldm_x4(r4, sb + (row & 127)*128 + ((c ^ (row & 7)) << 4) + (row >= 128 ? 16384u : 0u));
                b[np*2][0]   = r4[0]; b[np*2][1]   = r4[1];
                b[np*2+1][0] = r4[2]; b[np*2+1][1] = r4[3];
            }
            #pragma unroll
            for (int mt = 0; mt < 4; mt++)
                #pragma unroll
                for (int nt = 0; nt < 8; nt++)
                    mma_f16(acc[mt][nt], a[mt], b[nt]);
        }
    }

    // ---- epilogue: exchange h3 via smem, fuse silu in h1 warps ----
    __syncthreads();
    float* fs = (float*)dynsmem;
    int g = lane >> 2, t4 = lane & 3;
    if (wn >= 2) {
        float* reg = fs + (size_t)(wm*2 + (wn - 2)) * 4096;
        #pragma unroll
        for (int mt = 0; mt < 4; mt++)
            #pragma unroll
            for (int nt = 0; nt < 8; nt++)
                #pragma unroll
                for (int j = 0; j < 4; j++)
                    reg[(mt*32 + nt*4 + j)*32 + lane] = acc[mt][nt][j];
    }
    __syncthreads();
    if (wn < 2) {
        const float* reg = fs + (size_t)(wm*2 + wn) * 4096;
        const float* bp1 = g_bx1 + e*DM + c0;
        const float* bp3 = g_bx3 + e*DM + c0;
        #pragma unroll
        for (int mt = 0; mt < 4; mt++) {
            #pragma unroll
            for (int nt = 0; nt < 8; nt++) {
                int col = wn*64 + nt*8 + t4*2;
                float c1a = bp1[col], c1b = bp1[col+1];
                float c3a = bp3[col], c3b = bp3[col+1];
                float h3_0 = reg[(mt*32 + nt*4 + 0)*32 + lane] + c3a;
                float h3_1 = reg[(mt*32 + nt*4 + 1)*32 + lane] + c3b;
                float h3_2 = reg[(mt*32 + nt*4 + 2)*32 + lane] + c3a;
                float h3_3 = reg[(mt*32 + nt*4 + 3)*32 + lane] + c3b;
                int row0 = r0 + wm*64 + mt*16 + g;
                int C = c0 + col;
                float ha0 = silu(acc[mt][nt][0] + c1a) * h3_0;
                float hb0 = silu(acc[mt][nt][1] + c1b) * h3_1;
                float ha1 = silu(acc[mt][nt][2] + c1a) * h3_2;
                float hb1 = silu(acc[mt][nt][3] + c1b) * h3_3;
                char* p0 = (char*)g_H3 + (size_t)row0 * (KP*2) + (size_t)C * 2;
                char* p1 = (char*)g_H3 + (size_t)(row0+8) * (KP*2) + (size_t)C * 2;
                *(uint32_t*)p0 = pk(h16(ha0), h16(hb0));
                *(uint32_t*)p1 = pk(h16(ha1), h16(hb1));
            }
        }
    }
}

// ---------------- W2 GEMM: big tile 128 x 256 ----------------
__global__ __launch_bounds__(256)
void k_gemm2(const __half* __restrict__ A3, const __half* __restrict__ W2h,
             float* __restrict__ C)
{
    if ((int)blockIdx.x >= g_ntiles[0]) return;
    extern __shared__ char dynsmem[];

    int entry = g_rmap[blockIdx.x];
    int e = entry >> 20, r0 = entry & 0xFFFFF;
    int c0 = blockIdx.y << 8;                 // 256 cols
    int tid = threadIdx.x, wid = tid >> 5, lane = tid & 31;
    int wm = wid & 1, wn = wid >> 1;

    uint32_t sbase = smem_u32(dynsmem);
    const char* Ag = (const char*)(A3 + (size_t)r0 * KP);
    const char* Bg = (const char*)(W2h + (size_t)e * WS + (size_t)c0 * KP);

    int lrow = tid >> 3, lc = tid & 7;
    uint32_t aoff = (uint32_t)(lrow*128 + ((lc ^ (lrow & 7)) << 4));

    auto load_stage = [&](int s, int ch) {
        uint32_t sa = sbase + s * 49152;
        uint32_t sb = sa + 16384;
        const char* Ac = Ag + ch * 128;
        size_t goff = (size_t)lrow * (KP*2) + lc * 16;
        #pragma unroll
        for (int i = 0; i < 4; i++)
            cp16(sa + aoff + i*4096, Ac + goff + (size_t)i*32*(KP*2));
        #pragma unroll
        for (int i = 0; i < 8; i++) {
            int id = tid + i*256;
            int r = id >> 3, c = id & 7;
            int rl = r & 127;
            uint32_t off = (uint32_t)(rl*128 + ((c ^ (rl & 7)) << 4)) + (i >= 4 ? 16384u : 0u);
            cp16(sb + off, Bg + (size_t)r * (KP*2) + c*16 + (size_t)ch*128);
        }
        asm volatile("cp.async.commit_group;" ::: "memory");
    };

    float acc[4][8][4];
    #pragma unroll
    for (int mt = 0; mt < 4; mt++)
        #pragma unroll
        for (int nt = 0; nt < 8; nt++)
            #pragma unroll
            for (int j = 0; j < 4; j++) acc[mt][nt][j] = 0.f;

    load_stage(0, 0);

    int a_row  = wm*64 + (lane & 15);
    int a_cb   = lane >> 4;
    int b_row0 = wn*64 + ((lane >> 4) << 3) + (lane & 7);
    int b_cb   = (lane >> 3) & 1;

    for (int ch = 0; ch < NCH; ch++) {
        int s = ch & 1;
        if (ch > 0) __syncthreads();
        if (ch + 1 < NCH) load_stage(s ^ 1, ch + 1);
        else asm volatile("cp.async.commit_group;" ::: "memory");
        asm volatile("cp.async.wait_group 1;" ::: "memory");
        __syncthreads();

        uint32_t sa = sbase + s * 49152;
        uint32_t sb = sa + 16384;
        #pragma unroll
        for (int kk = 0; kk < 4; kk++) {
            uint32_t a[4][4], b[8][2];
            #pragma unroll
            for (int mt = 0; mt < 4; mt++) {
                int row = a_row + mt*16;
                int c = kk*2 + a_cb;
                ldm_x4(a[mt], sa + row*128 + ((c ^ (row & 7)) << 4));
            }
            #pragma unroll
            for (int np = 0; np < 4; np++) {
                int row = b_row0 + np*16;
                int c = kk*2 + b_cb;
                uint32_t r4[4];
                ldm_x4(r4, sb + (row & 127)*128 + ((c ^ (row & 7)) << 4) + (row >= 128 ? 16384u : 0u));
                b[np*2][0]   = r4[0]; b[np*2][1]   = r4[1];
                b[np*2+1][0] = r4[2]; b[np*2+1][1] = r4[3];
            }
            #pragma unroll
            for (int mt = 0; mt < 4; mt++)
                #pragma unroll
                for (int nt = 0; nt < 8; nt++)
                    mma_f16(acc[mt][nt], a[mt], b[nt]);
        }
    }

    int g = lane >> 2, t4 = lane & 3;
    const float* bp = g_bx2 + e*DM + c0;
    #pragma unroll
    for (int mt = 0; mt < 4; mt++) {
        #pragma unroll
        for (int nt = 0; nt < 8; nt++) {
            int col = wn*64 + nt*8 + t4*2;
            float b0 = bp[col], b1 = bp[col+1];
            int row0 = r0 + wm*64 + mt*16 + g;
            float2 v0 = make_float2(acc[mt][nt][0] + b0, acc[mt][nt][1] + b1);
            float2 v1 = make_float2(acc[mt][nt][2] + b0, acc[mt][nt][3] + b1);
            *(float2*)(C + (size_t)row0 * DM + c0 + col)     = v0;
            *(float2*)(C + (size_t)(row0+8) * DM + c0 + col) = v1;
        }
    }
}

// ---------------- combine ----------------
__global__ void k_combine(const float* __restrict__ Yg, float* __restrict__ out)
{
    int t = blockIdx.x;
    int r0 = g_slot_row[2*t], r1 = g_slot_row[2*t+1];
    float w0 = g_top_w[2*t], w1 = g_top_w[2*t+1];
    const float4* y0 = (const float4*)(Yg + (size_t)r0 * DM);
    const float4* y1 = (const float4*)(Yg + (size_t)r1 * DM);
    const float4* zz = (const float4*)(Yg + (size_t)t  * DM);
    float4*       o  = (float4*)(out + (size_t)t * DM);
    for (int d = threadIdx.x; d < DM/4; d += blockDim.x) {
        float4 a = y0[d], b = y1[d], c = zz[d], r;
        r.x = w0*a.x + w1*b.x + c.x;
        r.y = w0*a.y + w1*b.y + c.y;
        r.z = w0*a.z + w1*b.z + c.z;
        r.w = w0*a.w + w1*b.w + c.w;
        o[d] = r;
    }
}

// ---------------- launch ----------------
extern "C" void kernel_launch(void* const* d_in, const int* in_sizes, int n_in,
                              void* d_out, int out_size)
{
    const float* x    = (const float*)d_in[0];
    const float* gw   = (const float*)d_in[1];
    const float* w1   = (const float*)d_in[2];
    const float* b1   = (const float*)d_in[3];
    const float* w2   = (const float*)d_in[4];
    const float* b2   = (const float*)d_in[5];
    const float* w3   = (const float*)d_in[6];
    const float* b3   = (const float*)d_in[7];
    const float* sw1  = (const float*)d_in[8];
    const float* sb1  = (const float*)d_in[9];
    const float* sw2  = (const float*)d_in[10];
    const float* sb2  = (const float*)d_in[11];
    const float* sw3  = (const float*)d_in[12];
    const float* sb3  = (const float*)d_in[13];
    float* out = (float*)d_out;

    __half *Xg3, *H3, *w13, *w23, *w33;
    float *Yg;
    cudaGetSymbolAddress((void**)&Xg3, g_Xg3);
    cudaGetSymbolAddress((void**)&H3,  g_H3);
    cudaGetSymbolAddress((void**)&w13, g_w13);
    cudaGetSymbolAddress((void**)&w23, g_w23);
    cudaGetSymbolAddress((void**)&w33, g_w33);
    cudaGetSymbolAddress((void**)&Yg, g_Yg);

    const int SMEM = 2 * 49152;   // 96 KB, 2-stage
    cudaFuncSetAttribute(k_gemm13, cudaFuncAttributeMaxDynamicSharedMemorySize, SMEM);
    cudaFuncSetAttribute(k_gemm2,  cudaFuncAttributeMaxDynamicSharedMemorySize, SMEM);

    k_zero<<<1, 32>>>();
    k_gate<<<NTOK/8, 256>>>(x, gw);
    k_scan<<<1, 32>>>();

    k_cvt_a<<<(NTOK*DM/8 + 255)/256, 256>>>(x, Xg3, NTOK*DM/8);
    k_cvt_w<<<dim3(32,32,NE), dim3(32,8)>>>(w1, w13);
    k_cvt_w<<<dim3(32,32,NE), dim3(32,8)>>>(w3, w33);
    k_cvt_w<<<dim3(32,32,NE), dim3(32,8)>>>(w2, w23);
    k_cvt_w<<<dim3(32,32,1),  dim3(32,8)>>>(sw1, w13 + (size_t)NE * WS);
    k_cvt_w<<<dim3(32,32,1),  dim3(32,8)>>>(sw3, w33 + (size_t)NE * WS);
    k_cvt_w<<<dim3(32,32,1),  dim3(32,8)>>>(sw2, w23 + (size_t)NE * WS);
    k_biaspack<<<(NEX*DM + 255)/256, 256>>>(b1, b3, b2, sb1, sb3, sb2);

    k_zeropad<<<dim3(NE, 127), 256>>>();
    k_gather<<<NTOK*2, 128>>>();

    k_gemm13<<<dim3(TGRID, 8), 256, SMEM>>>(Xg3, w13, w33);
    k_gemm2 <<<dim3(TGRID, 4), 256, SMEM>>>(H3, w23, Yg);

    k_combine<<<NTOK, 256>>>(Yg, out);
}

// round 14
// speedup vs baseline: 1.3854x; 1.3854x over previous
#include <cuda_runtime.h>
#include <cuda_fp16.h>
#include <cstdint>
#include <math.h>

// ---------------- problem constants ----------------
#define NTOK   8192
#define DM     1024
#define NE     8
#define NEX    9          // 8 routed + shared-as-expert-8
#define KP     1024       // pure fp16
#define NCH    16         // KP / 64 chunks
#define SHROWS 8192
#define MAXROWS 25600
#define TGRID  208
#define WS     (DM * KP)

// ---------------- device scratch ----------------
__device__ __half g_Xg3[(size_t)MAXROWS * KP];
__device__ __half g_H3 [(size_t)MAXROWS * KP];
__device__ __half g_w13[(size_t)NEX * WS];
__device__ __half g_w23[(size_t)NEX * WS];
__device__ __half g_w33[(size_t)NEX * WS];
__device__ __half g_Yh[(size_t)MAXROWS * DM];    // fp16 expert outputs
__device__ float g_bx1[NEX * DM];
__device__ float g_bx2[NEX * DM];
__device__ float g_bx3[NEX * DM];

__device__ int   g_top_idx[NTOK * 2];
__device__ float g_top_w  [NTOK * 2];
__device__ int   g_slot_row[NTOK * 2];
__device__ int   g_counts[NE];
__device__ int   g_cursor[NE];
__device__ int   g_rowbase[NE];
__device__ int   g_rmap[224];
__device__ int   g_ntiles[1];

// ---------------- helpers ----------------
__device__ __forceinline__ uint32_t smem_u32(const void* p) {
    uint32_t a;
    asm("{ .reg .u64 t; cvta.to.shared.u64 t, %1; cvt.u32.u64 %0, t; }"
        : "=r"(a) : "l"(p));
    return a;
}
__device__ __forceinline__ void cp16(uint32_t dst, const void* src) {
    asm volatile("cp.async.cg.shared.global [%0], [%1], 16;\n"
                 :: "r"(dst), "l"(src) : "memory");
}
__device__ __forceinline__ void ldm_x4(uint32_t* r, uint32_t addr) {
    asm volatile("ldmatrix.sync.aligned.m8n8.x4.shared.b16 {%0,%1,%2,%3}, [%4];"
                 : "=r"(r[0]), "=r"(r[1]), "=r"(r[2]), "=r"(r[3]) : "r"(addr));
}
__device__ __forceinline__ void mma_f16(float* d, const uint32_t* a, const uint32_t* b) {
    asm volatile(
        "mma.sync.aligned.m16n8k16.row.col.f32.f16.f16.f32 "
        "{%0,%1,%2,%3}, {%4,%5,%6,%7}, {%8,%9}, {%0,%1,%2,%3};"
        : "+f"(d[0]), "+f"(d[1]), "+f"(d[2]), "+f"(d[3])
        : "r"(a[0]), "r"(a[1]), "r"(a[2]), "r"(a[3]), "r"(b[0]), "r"(b[1]));
}
__device__ __forceinline__ unsigned short h16(float v) {
    __half h = __float2half_rn(v);
    return *reinterpret_cast<unsigned short*>(&h);
}
__device__ __forceinline__ uint32_t pk(unsigned short a, unsigned short b) {
    return (uint32_t)a | ((uint32_t)b << 16);
}
__device__ __forceinline__ float silu(float x) {
    return x / (1.f + expf(-x));
}

// ---------------- routing kernels ----------------
__global__ void k_zero()
{
    int i = threadIdx.x;
    if (i < NE) { g_counts[i] = 0; g_cursor[i] = 0; }
}

// gate + activation fp32->fp16 convert fused (8 tokens per block, one per warp)
__global__ void k_gatecvt(const float* __restrict__ x, const float* __restrict__ gw)
{
    int w = threadIdx.x >> 5, lane = threadIdx.x & 31;
    int t = blockIdx.x * 8 + w;
    const float4* xr = (const float4*)(x + (size_t)t * DM);

    // load token row once: 8 float4 per lane (stride-32 coalesced)
    float4 v[8];
    #pragma unroll
    for (int i = 0; i < 8; i++) v[i] = xr[lane + i*32];

    // 8 expert logits
    float logits[NE];
    #pragma unroll
    for (int e = 0; e < NE; e++) {
        const float4* g = (const float4*)(gw + (size_t)e * DM);
        float s = 0.f;
        #pragma unroll
        for (int i = 0; i < 8; i++) {
            float4 b = g[lane + i*32];
            s += v[i].x*b.x + v[i].y*b.y + v[i].z*b.z + v[i].w*b.w;
        }
        #pragma unroll
        for (int o = 16; o; o >>= 1) s += __shfl_xor_sync(0xffffffffu, s, o);
        logits[e] = s;
    }

    // convert row to fp16 into Xg3[t]
    uint2* dst = (uint2*)(g_Xg3 + (size_t)t * KP);
    #pragma unroll
    for (int i = 0; i < 8; i++)
        dst[lane + i*32] = make_uint2(pk(h16(v[i].x), h16(v[i].y)),
                                      pk(h16(v[i].z), h16(v[i].w)));

    if (lane == 0) {
        float m = logits[0];
        #pragma unroll
        for (int e = 1; e < NE; e++) m = fmaxf(m, logits[e]);
        float sum = 0.f, p[NE];
        #pragma unroll
        for (int e = 0; e < NE; e++) { p[e] = expf(logits[e] - m); sum += p[e]; }
        int i0 = 0;
        #pragma unroll
        for (int e = 1; e < NE; e++) if (logits[e] > logits[i0]) i0 = e;
        int i1 = (i0 == 0) ? 1 : 0;
        #pragma unroll
        for (int e = 0; e < NE; e++)
            if (e != i0 && logits[e] > logits[i1]) i1 = e;
        float inv = 1.f / sum;
        g_top_idx[2*t]   = i0;  g_top_w[2*t]   = p[i0] * inv;
        g_top_idx[2*t+1] = i1;  g_top_w[2*t+1] = p[i1] * inv;
        atomicAdd(&g_counts[i0], 1);
        atomicAdd(&g_counts[i1], 1);
    }
}

__global__ void k_scan()
{
    if (threadIdx.x == 0) {
        int nt = 0;
        for (int i = 0; i < SHROWS / 128; i++)
            g_rmap[nt++] = (8 << 20) | (i << 7);
        int base = SHROWS;
        for (int e = 0; e < NE; e++) {
            g_rowbase[e] = base;
            int c = g_counts[e];
            int p = ((c + 127) >> 7) << 7;
            for (int i = 0; i < (p >> 7); i++)
                g_rmap[nt++] = (e << 20) | (base + (i << 7));
            base += p;
        }
        g_ntiles[0] = nt;
    }
}

// ---------------- weight conversion ----------------
__global__ void k_cvt_w(const float* __restrict__ W, __half* __restrict__ out)
{
    __shared__ float tile[32][33];
    int k0 = blockIdx.x << 5, n0 = blockIdx.y << 5;
    const float* Wm = W + (size_t)blockIdx.z * DM * DM;
    char* Om = (char*)out + (size_t)blockIdx.z * DM * (KP*2);
    int tx = threadIdx.x, ty = threadIdx.y;
    #pragma unroll
    for (int i = 0; i < 4; i++)
        tile[ty + i*8][tx] = Wm[(size_t)(k0 + ty + i*8) * DM + n0 + tx];
    __syncthreads();
    int tid = ty * 32 + tx;
    int wn = tid >> 3, wk4 = (tid & 7) << 2;
    char* ob = Om + (size_t)(n0 + wn) * (KP*2) + (size_t)(k0 + wk4) * 2;
    ((uint2*)ob)[0] = make_uint2(pk(h16(tile[wk4+0][wn]), h16(tile[wk4+1][wn])),
                                 pk(h16(tile[wk4+2][wn]), h16(tile[wk4+3][wn])));
}

__global__ void k_biaspack(const float* __restrict__ b1, const float* __restrict__ b3,
                           const float* __restrict__ b2, const float* __restrict__ sb1,
                           const float* __restrict__ sb3, const float* __restrict__ sb2)
{
    int i = blockIdx.x * blockDim.x + threadIdx.x;
    if (i >= NEX * DM) return;
    if (i < NE * DM) {
        g_bx1[i] = b1[i]; g_bx3[i] = b3[i]; g_bx2[i] = b2[i];
    } else {
        int j = i - NE * DM;
        g_bx1[i] = sb1[j]; g_bx3[i] = sb3[j]; g_bx2[i] = sb2[j];
    }
}

__global__ void k_zeropad()
{
    int e = blockIdx.x;
    int c = g_counts[e];
    int p = ((c + 127) >> 7) << 7;
    int r = c + blockIdx.y;
    if (r < p) {
        uint4* row = (uint4*)(g_Xg3 + (size_t)(g_rowbase[e] + r) * KP);
        for (int i = threadIdx.x; i < KP*2/16; i += blockDim.x)
            row[i] = make_uint4(0,0,0,0);
    }
}

__global__ void k_gather()
{
    int slot = blockIdx.x, t = slot >> 1;
    __shared__ int srow;
    if (threadIdx.x == 0) {
        int e  = g_top_idx[slot];
        int rk = atomicAdd(&g_cursor[e], 1);
        int row = g_rowbase[e] + rk;
        g_slot_row[slot] = row;
        srow = row;
    }
    __syncthreads();
    const uint4* src = (const uint4*)(g_Xg3 + (size_t)t * KP);
    uint4*       dst = (uint4*)(g_Xg3 + (size_t)srow * KP);
    for (int i = threadIdx.x; i < KP*2/16; i += blockDim.x) dst[i] = src[i];
}

// ---------------- fused W1/W3 + SiLU GEMM (R8 exact) ----------------
__global__ __launch_bounds__(256)
void k_gemm13(const __half* __restrict__ A3,
              const __half* __restrict__ W1h, const __half* __restrict__ W3h)
{
    if ((int)blockIdx.x >= g_ntiles[0]) return;
    extern __shared__ char dynsmem[];

    int entry = g_rmap[blockIdx.x];
    int e = entry >> 20, r0 = entry & 0xFFFFF;
    int c0 = blockIdx.y << 6;
    int tid = threadIdx.x, wid = tid >> 5, lane = tid & 31;
    int wm = wid & 3, wn = wid >> 2;

    uint32_t sbase = smem_u32(dynsmem);
    const char* Ag  = (const char*)(A3 + (size_t)r0 * KP);
    const char* B1g = (const char*)(W1h + (size_t)e * WS + (size_t)c0 * KP);
    const char* B3g = (const char*)(W3h + (size_t)e * WS + (size_t)c0 * KP);

    int lrow = tid >> 3, lc = tid & 7;
    uint32_t aoff = (uint32_t)(lrow*128 + ((lc ^ (lrow & 7)) << 4));

    auto load_stage = [&](int s, int ch) {
        uint32_t sa  = sbase + s * 32768;
        uint32_t sb1 = sa + 16384;
        uint32_t sb3 = sa + 24576;
        const char* Ac  = Ag  + ch * 128;
        const char* B1c = B1g + ch * 128;
        const char* B3c = B3g + ch * 128;
        size_t goff = (size_t)lrow * (KP*2) + lc * 16;
        #pragma unroll
        for (int i = 0; i < 4; i++)
            cp16(sa + aoff + i*4096, Ac + goff + (size_t)i*32*(KP*2));
        #pragma unroll
        for (int i = 0; i < 2; i++) {
            int id = tid + i*256;
            int r = id >> 3, c = id & 7;
            uint32_t off = (uint32_t)(r*128 + ((c ^ (r & 7)) << 4));
            size_t go = (size_t)r * (KP*2) + c * 16;
            cp16(sb1 + off, B1c + go);
            cp16(sb3 + off, B3c + go);
        }
        asm volatile("cp.async.commit_group;" ::: "memory");
    };

    float acc1[2][4][4], acc3[2][4][4];
    #pragma unroll
    for (int mt = 0; mt < 2; mt++)
        #pragma unroll
        for (int nt = 0; nt < 4; nt++)
            #pragma unroll
            for (int j = 0; j < 4; j++) { acc1[mt][nt][j] = 0.f; acc3[mt][nt][j] = 0.f; }

    load_stage(0, 0);
    load_stage(1, 1);
    load_stage(2, 2);

    int a_row = wm*32 + (lane & 15);
    int a_cb  = (lane >> 4);
    int b_rowb = wn*32 + ((lane >> 4) << 3) + (lane & 7);
    int b_cb  = ((lane >> 3) & 1);

    for (int ch = 0; ch < NCH; ch++) {
        int s = ch % 3;
        asm volatile("cp.async.wait_group 2;" ::: "memory");
        __syncthreads();
        uint32_t sa  = sbase + s * 32768;
        uint32_t sb1 = sa + 16384;
        uint32_t sb3 = sa + 24576;

        #pragma unroll
        for (int kk = 0; kk < 4; kk++) {
            uint32_t a[2][4], b1[4][2], b3[4][2];
            #pragma unroll
            for (int mt = 0; mt < 2; mt++) {
                int row = a_row + mt*16;
                int c = kk*2 + a_cb;
                ldm_x4(a[mt], sa + row*128 + ((c ^ (row & 7)) << 4));
            }
            #pragma unroll
            for (int np = 0; np < 2; np++) {
                int row = b_rowb + np*16;
                int c = kk*2 + b_cb;
                uint32_t sw = row*128 + ((c ^ (row & 7)) << 4);
                uint32_t r4[4];
                ldm_x4(r4, sb1 + sw);
                b1[np*2][0] = r4[0]; b1[np*2][1] = r4[1];
                b1[np*2+1][0] = r4[2]; b1[np*2+1][1] = r4[3];
                ldm_x4(r4, sb3 + sw);
                b3[np*2][0] = r4[0]; b3[np*2][1] = r4[1];
                b3[np*2+1][0] = r4[2]; b3[np*2+1][1] = r4[3];
            }
            #pragma unroll
            for (int mt = 0; mt < 2; mt++)
                #pragma unroll
                for (int nt = 0; nt < 4; nt++) {
                    mma_f16(acc1[mt][nt], a[mt], b1[nt]);
                    mma_f16(acc3[mt][nt], a[mt], b3[nt]);
                }
        }
        __syncthreads();
        if (ch + 3 < NCH) load_stage(s, ch + 3);
        else asm volatile("cp.async.commit_group;" ::: "memory");
    }

    int g = lane >> 2, t4 = lane & 3;
    const float* bp1 = g_bx1 + e*DM + c0;
    const float* bp3 = g_bx3 + e*DM + c0;
    #pragma unroll
    for (int mt = 0; mt < 2; mt++) {
        #pragma unroll
        for (int nt = 0; nt < 4; nt++) {
            int col = wn*32 + nt*8 + t4*2;
            float c1a = bp1[col], c1b = bp1[col+1];
            float c3a = bp3[col], c3b = bp3[col+1];
            int row0 = r0 + wm*32 + mt*16 + g;
            int C = c0 + col;
            float ha0 = silu(acc1[mt][nt][0] + c1a) * (acc3[mt][nt][0] + c3a);
            float hb0 = silu(acc1[mt][nt][1] + c1b) * (acc3[mt][nt][1] + c3b);
            float ha1 = silu(acc1[mt][nt][2] + c1a) * (acc3[mt][nt][2] + c3a);
            float hb1 = silu(acc1[mt][nt][3] + c1b) * (acc3[mt][nt][3] + c3b);
            char* p0 = (char*)g_H3 + (size_t)row0 * (KP*2) + (size_t)C * 2;
            char* p1 = (char*)g_H3 + (size_t)(row0+8) * (KP*2) + (size_t)C * 2;
            *(uint32_t*)p0 = pk(h16(ha0), h16(hb0));
            *(uint32_t*)p1 = pk(h16(ha1), h16(hb1));
        }
    }
}

// ---------------- W2 GEMM (R8 mainloop; fp16 output) ----------------
__global__ __launch_bounds__(256)
void k_gemm2(const __half* __restrict__ A3, const __half* __restrict__ W2h)
{
    if ((int)blockIdx.x >= g_ntiles[0]) return;
    extern __shared__ char dynsmem[];

    int entry = g_rmap[blockIdx.x];
    int e = entry >> 20, r0 = entry & 0xFFFFF;
    int c0 = blockIdx.y << 7;
    int tid = threadIdx.x, wid = tid >> 5, lane = tid & 31;
    int wr = wid & 1, wc = wid >> 1;

    uint32_t sbase = smem_u32(dynsmem);
    const char* Ag = (const char*)(A3 + (size_t)r0 * KP);
    const char* Bg = (const char*)(W2h + (size_t)e * WS + (size_t)c0 * KP);

    int lrow = tid >> 3, lc = tid & 7;
    uint32_t lsw = (uint32_t)(lrow*128 + ((lc ^ (lrow & 7)) << 4));

    auto load_stage = [&](int s, int ch) {
        uint32_t sa = sbase + s * 32768;
        uint32_t sb = sa + 16384;
        const char* Ac = Ag + ch * 128;
        const char* Bc = Bg + ch * 128;
        size_t goff = (size_t)lrow * (KP*2) + lc * 16;
        #pragma unroll
        for (int i = 0; i < 4; i++)
            cp16(sa + lsw + i*4096, Ac + goff + (size_t)i*32*(KP*2));
        #pragma unroll
        for (int i = 0; i < 4; i++)
            cp16(sb + lsw + i*4096, Bc + goff + (size_t)i*32*(KP*2));
        asm volatile("cp.async.commit_group;" ::: "memory");
    };

    float acc[4][4][4];
    #pragma unroll
    for (int mt = 0; mt < 4; mt++)
        #pragma unroll
        for (int nt = 0; nt < 4; nt++)
            #pragma unroll
            for (int j = 0; j < 4; j++) acc[mt][nt][j] = 0.f;

    load_stage(0, 0);
    load_stage(1, 1);
    load_stage(2, 2);

    int a_row = wr*64 + (lane & 15);
    int a_cb  = (lane >> 4);
    int b_row = wc*32 + ((lane >> 4) << 3) + (lane & 7);
    int b_cb  = ((lane >> 3) & 1);

    for (int ch = 0; ch < NCH; ch++) {
        int s = ch % 3;
        asm volatile("cp.async.wait_group 2;" ::: "memory");
        __syncthreads();
        uint32_t sa = sbase + s * 32768;
        uint32_t sb = sa + 16384;

        #pragma unroll
        for (int kk = 0; kk < 4; kk++) {
            uint32_t a[4][4], b[4][2];
            #pragma unroll
            for (int mt = 0; mt < 4; mt++) {
                int row = a_row + mt*16;
                int c = kk*2 + a_cb;
                ldm_x4(a[mt], sa + row*128 + ((c ^ (row & 7)) << 4));
            }
            #pragma unroll
            for (int np = 0; np < 2; np++) {
                int row = b_row + np*16;
                int c = kk*2 + b_cb;
                uint32_t r4[4];
                ldm_x4(r4, sb + row*128 + ((c ^ (row & 7)) << 4));
                b[np*2][0]   = r4[0]; b[np*2][1]   = r4[1];
                b[np*2+1][0] = r4[2]; b[np*2+1][1] = r4[3];
            }
            #pragma unroll
            for (int mt = 0; mt < 4; mt++)
                #pragma unroll
                for (int nt = 0; nt < 4; nt++)
                    mma_f16(acc[mt][nt], a[mt], b[nt]);
        }
        __syncthreads();
        if (ch + 3 < NCH) load_stage(s, ch + 3);
        else asm volatile("cp.async.commit_group;" ::: "memory");
    }

    int g = lane >> 2, t4 = lane & 3;
    const float* bp = g_bx2 + e*DM + c0;
    #pragma unroll
    for (int mt = 0; mt < 4; mt++) {
        #pragma unroll
        for (int nt = 0; nt < 4; nt++) {
            int col = wc*32 + nt*8 + t4*2;
            float b0 = bp[col], b1 = bp[col+1];
            int row0 = r0 + wr*64 + mt*16 + g;
            uint32_t p0 = pk(h16(acc[mt][nt][0] + b0), h16(acc[mt][nt][1] + b1));
            uint32_t p1 = pk(h16(acc[mt][nt][2] + b0), h16(acc[mt][nt][3] + b1));
            *(uint32_t*)((char*)g_Yh + (size_t)row0 * (DM*2) + (size_t)(c0 + col) * 2)     = p0;
            *(uint32_t*)((char*)g_Yh + (size_t)(row0+8) * (DM*2) + (size_t)(c0 + col) * 2) = p1;
        }
    }
}

// ---------------- combine (fp16 sources) ----------------
__global__ void k_combine(float* __restrict__ out)
{
    int t = blockIdx.x;
    int r0 = g_slot_row[2*t], r1 = g_slot_row[2*t+1];
    float w0 = g_top_w[2*t], w1 = g_top_w[2*t+1];
    const __half2* y0 = (const __half2*)(g_Yh + (size_t)r0 * DM);
    const __half2* y1 = (const __half2*)(g_Yh + (size_t)r1 * DM);
    const __half2* zz = (const __half2*)(g_Yh + (size_t)t  * DM);
    float2* o = (float2*)(out + (size_t)t * DM);
    for (int d = threadIdx.x; d < DM/2; d += blockDim.x) {
        float2 a = __half22float2(y0[d]);
        float2 b = __half22float2(y1[d]);
        float2 c = __half22float2(zz[d]);
        o[d] = make_float2(w0*a.x + w1*b.x + c.x, w0*a.y + w1*b.y + c.y);
    }
}

// ---------------- launch ----------------
extern "C" void kernel_launch(void* const* d_in, const int* in_sizes, int n_in,
                              void* d_out, int out_size)
{
    const float* x    = (const float*)d_in[0];
    const float* gw   = (const float*)d_in[1];
    const float* w1   = (const float*)d_in[2];
    const float* b1   = (const float*)d_in[3];
    const float* w2   = (const float*)d_in[4];
    const float* b2   = (const float*)d_in[5];
    const float* w3   = (const float*)d_in[6];
    const float* b3   = (const float*)d_in[7];
    const float* sw1  = (const float*)d_in[8];
    const float* sb1  = (const float*)d_in[9];
    const float* sw2  = (const float*)d_in[10];
    const float* sb2  = (const float*)d_in[11];
    const float* sw3  = (const float*)d_in[12];
    const float* sb3  = (const float*)d_in[13];
    float* out = (float*)d_out;

    __half *Xg3, *H3, *w13, *w23, *w33;
    cudaGetSymbolAddress((void**)&Xg3, g_Xg3);
    cudaGetSymbolAddress((void**)&H3,  g_H3);
    cudaGetSymbolAddress((void**)&w13, g_w13);
    cudaGetSymbolAddress((void**)&w23, g_w23);
    cudaGetSymbolAddress((void**)&w33, g_w33);

    const int SMEM = 3 * 32768;
    cudaFuncSetAttribute(k_gemm13, cudaFuncAttributeMaxDynamicSharedMemorySize, SMEM);
    cudaFuncSetAttribute(k_gemm2,  cudaFuncAttributeMaxDynamicSharedMemorySize, SMEM);

    k_zero<<<1, 32>>>();
    k_gatecvt<<<NTOK/8, 256>>>(x, gw);
    k_scan<<<1, 32>>>();

    k_cvt_w<<<dim3(32,32,NE), dim3(32,8)>>>(w1, w13);
    k_cvt_w<<<dim3(32,32,NE), dim3(32,8)>>>(w3, w33);
    k_cvt_w<<<dim3(32,32,NE), dim3(32,8)>>>(w2, w23);
    k_cvt_w<<<dim3(32,32,1),  dim3(32,8)>>>(sw1, w13 + (size_t)NE * WS);
    k_cvt_w<<<dim3(32,32,1),  dim3(32,8)>>>(sw3, w33 + (size_t)NE * WS);
    k_cvt_w<<<dim3(32,32,1),  dim3(32,8)>>>(sw2, w23 + (size_t)NE * WS);
    k_biaspack<<<(NEX*DM + 255)/256, 256>>>(b1, b3, b2, sb1, sb3, sb2);

    k_zeropad<<<dim3(NE, 127), 256>>>();
    k_gather<<<NTOK*2, 128>>>();

    k_gemm13<<<dim3(TGRID, 16), 256, SMEM>>>(Xg3, w13, w33);
    k_gemm2 <<<dim3(TGRID, 8),  256, SMEM>>>(H3, w23);

    k_combine<<<NTOK, 256>>>(out);
}

// round 16
// speedup vs baseline: 1.4126x; 1.0197x over previous
#include <cuda_runtime.h>
#include <cuda_fp16.h>
#include <cstdint>
#include <math.h>

// ---------------- problem constants ----------------
#define NTOK   8192
#define DM     1024
#define NE     8
#define NEX    9          // 8 routed + shared-as-expert-8
#define KP     1024       // pure fp16
#define NCH    16         // KP / 64 chunks
#define SHROWS 8192
#define MAXROWS 25600
#define TGRID  208
#define WS     (DM * KP)

// ---------------- device scratch ----------------
__device__ __half g_Xg3[(size_t)MAXROWS * KP];
__device__ __half g_H3 [(size_t)MAXROWS * KP];
__device__ __half g_w13[(size_t)NEX * WS];
__device__ __half g_w23[(size_t)NEX * WS];
__device__ __half g_w33[(size_t)NEX * WS];
__device__ __half g_Yh[(size_t)MAXROWS * DM];    // fp16 expert outputs
__device__ float g_bx1[NEX * DM];
__device__ float g_bx2[NEX * DM];
__device__ float g_bx3[NEX * DM];

__device__ int   g_top_idx[NTOK * 2];
__device__ float g_top_w  [NTOK * 2];
__device__ int   g_slot_row[NTOK * 2];
__device__ int   g_counts[NE];
__device__ int   g_cursor[NE];
__device__ int   g_rowbase[NE];
__device__ int   g_rmap[224];
__device__ int   g_ntiles[1];
__device__ int   g_padrows[1024];
__device__ int   g_npad[1];

// ---------------- helpers ----------------
__device__ __forceinline__ uint32_t smem_u32(const void* p) {
    uint32_t a;
    asm("{ .reg .u64 t; cvta.to.shared.u64 t, %1; cvt.u32.u64 %0, t; }"
        : "=r"(a) : "l"(p));
    return a;
}
__device__ __forceinline__ void cp16(uint32_t dst, const void* src) {
    asm volatile("cp.async.cg.shared.global [%0], [%1], 16;\n"
                 :: "r"(dst), "l"(src) : "memory");
}
__device__ __forceinline__ void ldm_x4(uint32_t* r, uint32_t addr) {
    asm volatile("ldmatrix.sync.aligned.m8n8.x4.shared.b16 {%0,%1,%2,%3}, [%4];"
                 : "=r"(r[0]), "=r"(r[1]), "=r"(r[2]), "=r"(r[3]) : "r"(addr));
}
__device__ __forceinline__ void mma_f16(float* d, const uint32_t* a, const uint32_t* b) {
    asm volatile(
        "mma.sync.aligned.m16n8k16.row.col.f32.f16.f16.f32 "
        "{%0,%1,%2,%3}, {%4,%5,%6,%7}, {%8,%9}, {%0,%1,%2,%3};"
        : "+f"(d[0]), "+f"(d[1]), "+f"(d[2]), "+f"(d[3])
        : "r"(a[0]), "r"(a[1]), "r"(a[2]), "r"(a[3]), "r"(b[0]), "r"(b[1]));
}
__device__ __forceinline__ unsigned short h16(float v) {
    __half h = __float2half_rn(v);
    return *reinterpret_cast<unsigned short*>(&h);
}
__device__ __forceinline__ uint32_t pk(unsigned short a, unsigned short b) {
    return (uint32_t)a | ((uint32_t)b << 16);
}
__device__ __forceinline__ float silu(float x) {
    return x / (1.f + expf(-x));
}

// ---------------- routing kernels ----------------
__global__ void k_zero()
{
    int i = threadIdx.x;
    if (i < NE) { g_counts[i] = 0; g_cursor[i] = 0; }
}

// gate + activation fp32->fp16 convert fused (8 tokens per block, one per warp)
__global__ void k_gatecvt(const float* __restrict__ x, const float* __restrict__ gw)
{
    int w = threadIdx.x >> 5, lane = threadIdx.x & 31;
    int t = blockIdx.x * 8 + w;
    const float4* xr = (const float4*)(x + (size_t)t * DM);

    float4 v[8];
    #pragma unroll
    for (int i = 0; i < 8; i++) v[i] = xr[lane + i*32];

    float logits[NE];
    #pragma unroll
    for (int e = 0; e < NE; e++) {
        const float4* g = (const float4*)(gw + (size_t)e * DM);
        float s = 0.f;
        #pragma unroll
        for (int i = 0; i < 8; i++) {
            float4 b = g[lane + i*32];
            s += v[i].x*b.x + v[i].y*b.y + v[i].z*b.z + v[i].w*b.w;
        }
        #pragma unroll
        for (int o = 16; o; o >>= 1) s += __shfl_xor_sync(0xffffffffu, s, o);
        logits[e] = s;
    }

    uint2* dst = (uint2*)(g_Xg3 + (size_t)t * KP);
    #pragma unroll
    for (int i = 0; i < 8; i++)
        dst[lane + i*32] = make_uint2(pk(h16(v[i].x), h16(v[i].y)),
                                      pk(h16(v[i].z), h16(v[i].w)));

    if (lane == 0) {
        float m = logits[0];
        #pragma unroll
        for (int e = 1; e < NE; e++) m = fmaxf(m, logits[e]);
        float sum = 0.f, p[NE];
        #pragma unroll
        for (int e = 0; e < NE; e++) { p[e] = expf(logits[e] - m); sum += p[e]; }
        int i0 = 0;
        #pragma unroll
        for (int e = 1; e < NE; e++) if (logits[e] > logits[i0]) i0 = e;
        int i1 = (i0 == 0) ? 1 : 0;
        #pragma unroll
        for (int e = 0; e < NE; e++)
            if (e != i0 && logits[e] > logits[i1]) i1 = e;
        float inv = 1.f / sum;
        g_top_idx[2*t]   = i0;  g_top_w[2*t]   = p[i0] * inv;
        g_top_idx[2*t+1] = i1;  g_top_w[2*t+1] = p[i1] * inv;
        atomicAdd(&g_counts[i0], 1);
        atomicAdd(&g_counts[i1], 1);
    }
}

// tile map + pad-row list
__global__ void k_scan()
{
    if (threadIdx.x == 0) {
        int nt = 0;
        for (int i = 0; i < SHROWS / 128; i++)
            g_rmap[nt++] = (8 << 20) | (i << 7);
        int base = SHROWS, np = 0;
        for (int e = 0; e < NE; e++) {
            g_rowbase[e] = base;
            int c = g_counts[e];
            int p = ((c + 127) >> 7) << 7;
            for (int i = 0; i < (p >> 7); i++)
                g_rmap[nt++] = (e << 20) | (base + (i << 7));
            for (int r = c; r < p; r++) g_padrows[np++] = base + r;
            base += p;
        }
        g_ntiles[0] = nt;
        g_npad[0] = np;
    }
}

// ---------------- all weight conversions + bias pack in ONE launch ----------------
// grid (32,32,27): f=z/9 (0:W1,1:W3,2:W2), s=z%9 (8=shared). z==0 blocks with
// small linear id also pack biases (independent, tiny).
__global__ void k_cvt_wall(const float* __restrict__ w1, const float* __restrict__ w3,
                           const float* __restrict__ w2, const float* __restrict__ sw1,
                           const float* __restrict__ sw3, const float* __restrict__ sw2,
                           const float* __restrict__ b1, const float* __restrict__ b3,
                           const float* __restrict__ b2, const float* __restrict__ sb1,
                           const float* __restrict__ sb3, const float* __restrict__ sb2)
{
    __shared__ float tile[32][33];
    int tid = threadIdx.y * 32 + threadIdx.x;
    int f = blockIdx.z / 9, s = blockIdx.z % 9;
    const float* src;
    __half* dstbase;
    if (f == 0)      { src = (s < 8) ? w1 + (size_t)s * DM * DM : sw1; dstbase = g_w13; }
    else if (f == 1) { src = (s < 8) ? w3 + (size_t)s * DM * DM : sw3; dstbase = g_w33; }
    else             { src = (s < 8) ? w2 + (size_t)s * DM * DM : sw2; dstbase = g_w23; }
    char* Om = (char*)(dstbase + (size_t)s * WS);

    int k0 = blockIdx.x << 5, n0 = blockIdx.y << 5;
    int tx = threadIdx.x, ty = threadIdx.y;
    #pragma unroll
    for (int i = 0; i < 4; i++)
        tile[ty + i*8][tx] = src[(size_t)(k0 + ty + i*8) * DM + n0 + tx];
    __syncthreads();
    int wn = tid >> 3, wk4 = (tid & 7) << 2;
    char* ob = Om + (size_t)(n0 + wn) * (KP*2) + (size_t)(k0 + wk4) * 2;
    ((uint2*)ob)[0] = make_uint2(pk(h16(tile[wk4+0][wn]), h16(tile[wk4+1][wn])),
                                 pk(h16(tile[wk4+2][wn]), h16(tile[wk4+3][wn])));

    // bias pack: 36 blocks of z==0 handle NEX*DM = 9216 floats
    if (blockIdx.z == 0) {
        int blockid = blockIdx.y * 32 + blockIdx.x;
        if (blockid < 36) {
            int j = blockid * 256 + tid;
            if (j < NEX * DM) {
                if (j < NE * DM) { g_bx1[j] = b1[j]; g_bx3[j] = b3[j]; g_bx2[j] = b2[j]; }
                else { int k = j - NE*DM; g_bx1[j] = sb1[k]; g_bx3[j] = sb3[k]; g_bx2[j] = sb2[k]; }
            }
        }
    }
}

// gather + zeropad in one launch: blocks [0, 16384) gather slots; rest zero pad rows.
__global__ void k_gathpad()
{
    int bid = blockIdx.x;
    if (bid < NTOK * 2) {
        int slot = bid, t = slot >> 1;
        __shared__ int srow;
        if (threadIdx.x == 0) {
            int e  = g_top_idx[slot];
            int rk = atomicAdd(&g_cursor[e], 1);
            int row = g_rowbase[e] + rk;
            g_slot_row[slot] = row;
            srow = row;
        }
        __syncthreads();
        const uint4* src = (const uint4*)(g_Xg3 + (size_t)t * KP);
        uint4*       dst = (uint4*)(g_Xg3 + (size_t)srow * KP);
        for (int i = threadIdx.x; i < KP*2/16; i += blockDim.x) dst[i] = src[i];
    } else {
        int j = bid - NTOK * 2;
        if (j < g_npad[0]) {
            uint4* row = (uint4*)(g_Xg3 + (size_t)g_padrows[j] * KP);
            for (int i = threadIdx.x; i < KP*2/16; i += blockDim.x)
                row[i] = make_uint4(0,0,0,0);
        }
    }
}

// ---------------- fused W1/W3 + SiLU GEMM (R8 exact) ----------------
__global__ __launch_bounds__(256)
void k_gemm13(const __half* __restrict__ A3,
              const __half* __restrict__ W1h, const __half* __restrict__ W3h)
{
    if ((int)blockIdx.x >= g_ntiles[0]) return;
    extern __shared__ char dynsmem[];

    int entry = g_rmap[blockIdx.x];
    int e = entry >> 20, r0 = entry & 0xFFFFF;
    int c0 = blockIdx.y << 6;
    int tid = threadIdx.x, wid = tid >> 5, lane = tid & 31;
    int wm = wid & 3, wn = wid >> 2;

    uint32_t sbase = smem_u32(dynsmem);
    const char* Ag  = (const char*)(A3 + (size_t)r0 * KP);
    const char* B1g = (const char*)(W1h + (size_t)e * WS + (size_t)c0 * KP);
    const char* B3g = (const char*)(W3h + (size_t)e * WS + (size_t)c0 * KP);

    int lrow = tid >> 3, lc = tid & 7;
    uint32_t aoff = (uint32_t)(lrow*128 + ((lc ^ (lrow & 7)) << 4));

    auto load_stage = [&](int s, int ch) {
        uint32_t sa  = sbase + s * 32768;
        uint32_t sb1 = sa + 16384;
        uint32_t sb3 = sa + 24576;
        const char* Ac  = Ag  + ch * 128;
        const char* B1c = B1g + ch * 128;
        const char* B3c = B3g + ch * 128;
        size_t goff = (size_t)lrow * (KP*2) + lc * 16;
        #pragma unroll
        for (int i = 0; i < 4; i++)
            cp16(sa + aoff + i*4096, Ac + goff + (size_t)i*32*(KP*2));
        #pragma unroll
        for (int i = 0; i < 2; i++) {
            int id = tid + i*256;
            int r = id >> 3, c = id & 7;
            uint32_t off = (uint32_t)(r*128 + ((c ^ (r & 7)) << 4));
            size_t go = (size_t)r * (KP*2) + c * 16;
            cp16(sb1 + off, B1c + go);
            cp16(sb3 + off, B3c + go);
        }
        asm volatile("cp.async.commit_group;" ::: "memory");
    };

    float acc1[2][4][4], acc3[2][4][4];
    #pragma unroll
    for (int mt = 0; mt < 2; mt++)
        #pragma unroll
        for (int nt = 0; nt < 4; nt++)
            #pragma unroll
            for (int j = 0; j < 4; j++) { acc1[mt][nt][j] = 0.f; acc3[mt][nt][j] = 0.f; }

    load_stage(0, 0);
    load_stage(1, 1);
    load_stage(2, 2);

    int a_row = wm*32 + (lane & 15);
    int a_cb  = (lane >> 4);
    int b_rowb = wn*32 + ((lane >> 4) << 3) + (lane & 7);
    int b_cb  = ((lane >> 3) & 1);

    for (int ch = 0; ch < NCH; ch++) {
        int s = ch % 3;
        asm volatile("cp.async.wait_group 2;" ::: "memory");
        __syncthreads();
        uint32_t sa  = sbase + s * 32768;
        uint32_t sb1 = sa + 16384;
        uint32_t sb3 = sa + 24576;

        #pragma unroll
        for (int kk = 0; kk < 4; kk++) {
            uint32_t a[2][4], b1[4][2], b3[4][2];
            #pragma unroll
            for (int mt = 0; mt < 2; mt++) {
                int row = a_row + mt*16;
                int c = kk*2 + a_cb;
                ldm_x4(a[mt], sa + row*128 + ((c ^ (row & 7)) << 4));
            }
            #pragma unroll
            for (int np = 0; np < 2; np++) {
                int row = b_rowb + np*16;
                int c = kk*2 + b_cb;
                uint32_t sw = row*128 + ((c ^ (row & 7)) << 4);
                uint32_t r4[4];
                ldm_x4(r4, sb1 + sw);
                b1[np*2][0] = r4[0]; b1[np*2][1] = r4[1];
                b1[np*2+1][0] = r4[2]; b1[np*2+1][1] = r4[3];
                ldm_x4(r4, sb3 + sw);
                b3[np*2][0] = r4[0]; b3[np*2][1] = r4[1];
                b3[np*2+1][0] = r4[2]; b3[np*2+1][1] = r4[3];
            }
            #pragma unroll
            for (int mt = 0; mt < 2; mt++)
                #pragma unroll
                for (int nt = 0; nt < 4; nt++) {
                    mma_f16(acc1[mt][nt], a[mt], b1[nt]);
                    mma_f16(acc3[mt][nt], a[mt], b3[nt]);
                }
        }
        __syncthreads();
        if (ch + 3 < NCH) load_stage(s, ch + 3);
        else asm volatile("cp.async.commit_group;" ::: "memory");
    }

    int g = lane >> 2, t4 = lane & 3;
    const float* bp1 = g_bx1 + e*DM + c0;
    const float* bp3 = g_bx3 + e*DM + c0;
    #pragma unroll
    for (int mt = 0; mt < 2; mt++) {
        #pragma unroll
        for (int nt = 0; nt < 4; nt++) {
            int col = wn*32 + nt*8 + t4*2;
            float c1a = bp1[col], c1b = bp1[col+1];
            float c3a = bp3[col], c3b = bp3[col+1];
            int row0 = r0 + wm*32 + mt*16 + g;
            int C = c0 + col;
            float ha0 = silu(acc1[mt][nt][0] + c1a) * (acc3[mt][nt][0] + c3a);
            float hb0 = silu(acc1[mt][nt][1] + c1b) * (acc3[mt][nt][1] + c3b);
            float ha1 = silu(acc1[mt][nt][2] + c1a) * (acc3[mt][nt][2] + c3a);
            float hb1 = silu(acc1[mt][nt][3] + c1b) * (acc3[mt][nt][3] + c3b);
            char* p0 = (char*)g_H3 + (size_t)row0 * (KP*2) + (size_t)C * 2;
            char* p1 = (char*)g_H3 + (size_t)(row0+8) * (KP*2) + (size_t)C * 2;
            *(uint32_t*)p0 = pk(h16(ha0), h16(hb0));
            *(uint32_t*)p1 = pk(h16(ha1), h16(hb1));
        }
    }
}

// ---------------- W2 GEMM (R8 mainloop; fp16 output) ----------------
__global__ __launch_bounds__(256)
void k_gemm2(const __half* __restrict__ A3, const __half* __restrict__ W2h)
{
    if ((int)blockIdx.x >= g_ntiles[0]) return;
    extern __shared__ char dynsmem[];

    int entry = g_rmap[blockIdx.x];
    int e = entry >> 20, r0 = entry & 0xFFFFF;
    int c0 = blockIdx.y << 7;
    int tid = threadIdx.x, wid = tid >> 5, lane = tid & 31;
    int wr = wid & 1, wc = wid >> 1;

    uint32_t sbase = smem_u32(dynsmem);
    const char* Ag = (const char*)(A3 + (size_t)r0 * KP);
    const char* Bg = (const char*)(W2h + (size_t)e * WS + (size_t)c0 * KP);

    int lrow = tid >> 3, lc = tid & 7;
    uint32_t lsw = (uint32_t)(lrow*128 + ((lc ^ (lrow & 7)) << 4));

    auto load_stage = [&](int s, int ch) {
        uint32_t sa = sbase + s * 32768;
        uint32_t sb = sa + 16384;
        const char* Ac = Ag + ch * 128;
        const char* Bc = Bg + ch * 128;
        size_t goff = (size_t)lrow * (KP*2) + lc * 16;
        #pragma unroll
        for (int i = 0; i < 4; i++)
            cp16(sa + lsw + i*4096, Ac + goff + (size_t)i*32*(KP*2));
        #pragma unroll
        for (int i = 0; i < 4; i++)
            cp16(sb + lsw + i*4096, Bc + goff + (size_t)i*32*(KP*2));
        asm volatile("cp.async.commit_group;" ::: "memory");
    };

    float acc[4][4][4];
    #pragma unroll
    for (int mt = 0; mt < 4; mt++)
        #pragma unroll
        for (int nt = 0; nt < 4; nt++)
            #pragma unroll
            for (int j = 0; j < 4; j++) acc[mt][nt][j] = 0.f;

    load_stage(0, 0);
    load_stage(1, 1);
    load_stage(2, 2);

    int a_row = wr*64 + (lane & 15);
    int a_cb  = (lane >> 4);
    int b_row = wc*32 + ((lane >> 4) << 3) + (lane & 7);
    int b_cb  = ((lane >> 3) & 1);

    for (int ch = 0; ch < NCH; ch++) {
        int s = ch % 3;
        asm volatile("cp.async.wait_group 2;" ::: "memory");
        __syncthreads();
        uint32_t sa = sbase + s * 32768;
        uint32_t sb = sa + 16384;

        #pragma unroll
        for (int kk = 0; kk < 4; kk++) {
            uint32_t a[4][4], b[4][2];
            #pragma unroll
            for (int mt = 0; mt < 4; mt++) {
                int row = a_row + mt*16;
                int c = kk*2 + a_cb;
                ldm_x4(a[mt], sa + row*128 + ((c ^ (row & 7)) << 4));
            }
            #pragma unroll
            for (int np = 0; np < 2; np++) {
                int row = b_row + np*16;
                int c = kk*2 + b_cb;
                uint32_t r4[4];
                ldm_x4(r4, sb + row*128 + ((c ^ (row & 7)) << 4));
                b[np*2][0]   = r4[0]; b[np*2][1]   = r4[1];
                b[np*2+1][0] = r4[2]; b[np*2+1][1] = r4[3];
            }
            #pragma unroll
            for (int mt = 0; mt < 4; mt++)
                #pragma unroll
                for (int nt = 0; nt < 4; nt++)
                    mma_f16(acc[mt][nt], a[mt], b[nt]);
        }
        __syncthreads();
        if (ch + 3 < NCH) load_stage(s, ch + 3);
        else asm volatile("cp.async.commit_group;" ::: "memory");
    }

    int g = lane >> 2, t4 = lane & 3;
    const float* bp = g_bx2 + e*DM + c0;
    #pragma unroll
    for (int mt = 0; mt < 4; mt++) {
        #pragma unroll
        for (int nt = 0; nt < 4; nt++) {
            int col = wc*32 + nt*8 + t4*2;
            float b0 = bp[col], b1 = bp[col+1];
            int row0 = r0 + wr*64 + mt*16 + g;
            uint32_t p0 = pk(h16(acc[mt][nt][0] + b0), h16(acc[mt][nt][1] + b1));
            uint32_t p1 = pk(h16(acc[mt][nt][2] + b0), h16(acc[mt][nt][3] + b1));
            *(uint32_t*)((char*)g_Yh + (size_t)row0 * (DM*2) + (size_t)(c0 + col) * 2)     = p0;
            *(uint32_t*)((char*)g_Yh + (size_t)(row0+8) * (DM*2) + (size_t)(c0 + col) * 2) = p1;
        }
    }
}

// ---------------- combine (fp16 sources) ----------------
__global__ void k_combine(float* __restrict__ out)
{
    int t = blockIdx.x;
    int r0 = g_slot_row[2*t], r1 = g_slot_row[2*t+1];
    float w0 = g_top_w[2*t], w1 = g_top_w[2*t+1];
    const __half2* y0 = (const __half2*)(g_Yh + (size_t)r0 * DM);
    const __half2* y1 = (const __half2*)(g_Yh + (size_t)r1 * DM);
    const __half2* zz = (const __half2*)(g_Yh + (size_t)t  * DM);
    float2* o = (float2*)(out + (size_t)t * DM);
    for (int d = threadIdx.x; d < DM/2; d += blockDim.x) {
        float2 a = __half22float2(y0[d]);
        float2 b = __half22float2(y1[d]);
        float2 c = __half22float2(zz[d]);
        o[d] = make_float2(w0*a.x + w1*b.x + c.x, w0*a.y + w1*b.y + c.y);
    }
}

// ---------------- launch ----------------
extern "C" void kernel_launch(void* const* d_in, const int* in_sizes, int n_in,
                              void* d_out, int out_size)
{
    const float* x    = (const float*)d_in[0];
    const float* gw   = (const float*)d_in[1];
    const float* w1   = (const float*)d_in[2];
    const float* b1   = (const float*)d_in[3];
    const float* w2   = (const float*)d_in[4];
    const float* b2   = (const float*)d_in[5];
    const float* w3   = (const float*)d_in[6];
    const float* b3   = (const float*)d_in[7];
    const float* sw1  = (const float*)d_in[8];
    const float* sb1  = (const float*)d_in[9];
    const float* sw2  = (const float*)d_in[10];
    const float* sb2  = (const float*)d_in[11];
    const float* sw3  = (const float*)d_in[12];
    const float* sb3  = (const float*)d_in[13];
    float* out = (float*)d_out;

    __half *Xg3, *H3, *w13, *w23, *w33;
    cudaGetSymbolAddress((void**)&Xg3, g_Xg3);
    cudaGetSymbolAddress((void**)&H3,  g_H3);
    cudaGetSymbolAddress((void**)&w13, g_w13);
    cudaGetSymbolAddress((void**)&w23, g_w23);
    cudaGetSymbolAddress((void**)&w33, g_w33);

    const int SMEM = 3 * 32768;
    cudaFuncSetAttribute(k_gemm13, cudaFuncAttributeMaxDynamicSharedMemorySize, SMEM);
    cudaFuncSetAttribute(k_gemm2,  cudaFuncAttributeMaxDynamicSharedMemorySize, SMEM);

    k_zero<<<1, 32>>>();                                              // 1
    k_gatecvt<<<NTOK/8, 256>>>(x, gw);                                // 2
    k_scan<<<1, 32>>>();                                              // 3
    k_cvt_wall<<<dim3(32,32,27), dim3(32,8)>>>(w1, w3, w2,            // 4
                                               sw1, sw3, sw2,
                                               b1, b3, b2, sb1, sb3, sb2);
    k_gathpad<<<NTOK*2 + 1024, 128>>>();                              // 5
    k_gemm13<<<dim3(TGRID, 16), 256, SMEM>>>(Xg3, w13, w33);          // 6
    k_gemm2 <<<dim3(TGRID, 8),  256, SMEM>>>(H3, w23);                // 7
    k_combine<<<NTOK, 256>>>(out);                                    // 8
}